// round 1
// baseline (speedup 1.0000x reference)
#include <cuda_runtime.h>
#include <math.h>
#include <stdint.h>

#define HW 4096
#define EPSBN 1e-5f

// ---------------- scratch (static device allocations) ----------------
__device__ float d_wall[192 * 256];                 // folded W for convs 1,2,3 stacked
__device__ float d_ball[192];
__device__ float d_w4f[256 * 128];                  // folded W4
__device__ float d_b4f[256];
__device__ float d_yall[(size_t)8 * 192 * 4096];    // conv1/2/3 outputs (ReLU'd): rows 0-31 fpre, 32-63 g, 64-191 hpre
__device__ float d_fp[(size_t)8 * 32 * 1024];       // pooled f  [b][k][n]
__device__ float d_hp[(size_t)8 * 128 * 1024];      // pooled hh [b][c][n]
__device__ float d_ov[(size_t)8 * 128 * 4096];      // attention output o [b][c][m]

// ---------------- prep: fold BN into conv weights ----------------
__global__ void prep_kernel(
    const float* w1, const float* b1, const float* s1, const float* t1, const float* m1, const float* v1,
    const float* w2, const float* b2, const float* s2, const float* t2, const float* m2, const float* v2,
    const float* w3, const float* b3, const float* s3, const float* t3, const float* m3, const float* v3,
    const float* w4, const float* b4, const float* s4, const float* t4, const float* m4, const float* v4)
{
    int i = blockIdx.x * 256 + threadIdx.x;
    if (i < 192 * 256) {
        int row = i >> 8, c = i & 255;
        const float *w, *s, *v; int oc;
        if (row < 32)      { w = w1; s = s1; v = v1; oc = row; }
        else if (row < 64) { w = w2; s = s2; v = v2; oc = row - 32; }
        else               { w = w3; s = s3; v = v3; oc = row - 64; }
        float sc = s[oc] * rsqrtf(v[oc] + EPSBN);
        d_wall[i] = w[oc * 256 + c] * sc;
    }
    if (i < 256 * 128) {
        int row = i >> 7, c = i & 127;
        float sc = s4[row] * rsqrtf(v4[row] + EPSBN);
        d_w4f[i] = w4[row * 128 + c] * sc;
    }
    if (i < 192) {
        const float *bb, *s, *v, *mm, *tt; int oc;
        if (i < 32)      { bb = b1; s = s1; v = v1; mm = m1; tt = t1; oc = i; }
        else if (i < 64) { bb = b2; s = s2; v = v2; mm = m2; tt = t2; oc = i - 32; }
        else             { bb = b3; s = s3; v = v3; mm = m3; tt = t3; oc = i - 64; }
        float sc = s[oc] * rsqrtf(v[oc] + EPSBN);
        d_ball[i] = (bb[oc] - mm[oc]) * sc + tt[oc];
    }
    if (i < 256) {
        float sc = s4[i] * rsqrtf(v4[i] + EPSBN);
        d_b4f[i] = (b4[i] - m4[i]) * sc + t4[i];
    }
}

// ---------------- conv1x1 GEMM (MODE 0: convs1-3 + ReLU -> d_yall,
//                                MODE 1: conv4 + gamma*(.)+x -> out) ----------------
template <int MODE>
__global__ void gemm_kernel(const float* __restrict__ X, float* __restrict__ Out,
                            const float* __restrict__ gamma_p)
{
    constexpr int M = (MODE == 0) ? 192 : 256;
    constexpr int K = (MODE == 0) ? 256 : 128;
    const float* W    = (MODE == 0) ? d_wall : d_w4f;
    const float* bias = (MODE == 0) ? d_ball : d_b4f;

    const int b  = blockIdx.z;
    const int m0 = blockIdx.y * 64;
    const int n0 = blockIdx.x * 128;
    const float* in = ((MODE == 0) ? X : (const float*)d_ov) + (size_t)b * K * HW;
    float* Obase = (MODE == 0) ? d_yall : Out;

    __shared__ float ws[32][65];
    __shared__ float xs[32][128];

    float acc[4][8];
#pragma unroll
    for (int i = 0; i < 4; i++)
#pragma unroll
        for (int j = 0; j < 8; j++) acc[i][j] = 0.f;

    const int t = threadIdx.x;
    const int ty = t >> 4, tx = t & 15;

    for (int k0 = 0; k0 < K; k0 += 32) {
#pragma unroll
        for (int i = 0; i < 8; i++) {
            int e = t + i * 256; int mm = e >> 5, kk = e & 31;
            ws[kk][mm] = W[(m0 + mm) * K + k0 + kk];
        }
#pragma unroll
        for (int i = 0; i < 16; i++) {
            int e = t + i * 256; int kk = e >> 7, pp = e & 127;
            xs[kk][pp] = in[(size_t)(k0 + kk) * HW + n0 + pp];
        }
        __syncthreads();
#pragma unroll
        for (int kk = 0; kk < 32; kk++) {
            float wr[4], xr[8];
#pragma unroll
            for (int i = 0; i < 4; i++) wr[i] = ws[kk][ty * 4 + i];
#pragma unroll
            for (int j = 0; j < 8; j++) xr[j] = xs[kk][tx * 8 + j];
#pragma unroll
            for (int i = 0; i < 4; i++)
#pragma unroll
                for (int j = 0; j < 8; j++) acc[i][j] += wr[i] * xr[j];
        }
        __syncthreads();
    }

    float gm = (MODE == 1) ? gamma_p[0] : 0.f;
#pragma unroll
    for (int i = 0; i < 4; i++) {
        int r = m0 + ty * 4 + i;
        float bv = bias[r];
        size_t off = ((size_t)b * M + r) * HW + n0 + tx * 8;
        float4 o0, o1;
        if (MODE == 0) {
            o0.x = fmaxf(acc[i][0] + bv, 0.f); o0.y = fmaxf(acc[i][1] + bv, 0.f);
            o0.z = fmaxf(acc[i][2] + bv, 0.f); o0.w = fmaxf(acc[i][3] + bv, 0.f);
            o1.x = fmaxf(acc[i][4] + bv, 0.f); o1.y = fmaxf(acc[i][5] + bv, 0.f);
            o1.z = fmaxf(acc[i][6] + bv, 0.f); o1.w = fmaxf(acc[i][7] + bv, 0.f);
        } else {
            const float4 r0 = *(const float4*)(X + off);
            const float4 r1 = *(const float4*)(X + off + 4);
            o0.x = gm * (acc[i][0] + bv) + r0.x; o0.y = gm * (acc[i][1] + bv) + r0.y;
            o0.z = gm * (acc[i][2] + bv) + r0.z; o0.w = gm * (acc[i][3] + bv) + r0.w;
            o1.x = gm * (acc[i][4] + bv) + r1.x; o1.y = gm * (acc[i][5] + bv) + r1.y;
            o1.z = gm * (acc[i][6] + bv) + r1.z; o1.w = gm * (acc[i][7] + bv) + r1.w;
        }
        *(float4*)(Obase + off)     = o0;
        *(float4*)(Obase + off + 4) = o1;
    }
}

// ---------------- 2x2 maxpool on fpre and hpre ----------------
__global__ void pool_kernel()
{
    int idx = blockIdx.x * 256 + threadIdx.x;
    if (idx >= 8 * 160 * 1024) return;
    int n = idx & 1023;
    int r = (idx >> 10) % 160;
    int b = idx / (160 * 1024);
    int ph = n >> 5, pw = n & 31;
    int sr = (r < 32) ? r : r + 32;   // hpre rows live at 64..191
    const float* base = d_yall + ((size_t)(b * 192 + sr)) * HW + ph * 128 + pw * 2;
    float v = fmaxf(fmaxf(base[0], base[1]), fmaxf(base[64], base[65]));
    if (r < 32) d_fp[((size_t)b * 32 + r) * 1024 + n] = v;
    else        d_hp[((size_t)b * 128 + (r - 32)) * 1024 + n] = v;
}

// ---------------- fused flash-style attention ----------------
// logits S[n][m] = sum_k f[n][k]*g[k][m]; softmax over n (1024); o[c][m] = sum_n hh[c][n] P[n][m]
#define PADF 132
#define PADV 132
#define PADP 68

__global__ void attn_kernel()
{
    extern __shared__ float sm[];
    float* sg    = sm;                    // [32][64]   queries g
    float* sf    = sg + 32 * 64;          // [32][PADF] keys f (k-major)
    float* sv    = sf + 32 * PADF;        // [128][PADV] values v[n][c]
    float* sp    = sv + 128 * PADV;       // [128][PADP] logits/probs
    float* sred  = sp + 128 * PADP;       // [8][64] max then sum partials
    float* scorr = sred + 512;            // [64]
    float* sl    = scorr + 64;            // [64]

    const int b  = blockIdx.y;
    const int m0 = blockIdx.x * 64;
    const int t  = threadIdx.x;

    // q tile: sg[k][m] = g[b][k][m0+m]  (g = yall rows 32..63)
#pragma unroll
    for (int i = 0; i < 8; i++) {
        int e = t + i * 256; int k = e >> 6, mm = e & 63;
        sg[k * 64 + mm] = d_yall[((size_t)(b * 192 + 32 + k)) * HW + m0 + mm];
    }

    const int tyc = t >> 3, txm = t & 7;    // GEMM mapping: 32x8 threads, 4x8 register tile
    const int msm = t & 63, q = t >> 6;     // softmax mapping: 4 threads per query column

    float accO[4][8];
#pragma unroll
    for (int i = 0; i < 4; i++)
#pragma unroll
        for (int j = 0; j < 8; j++) accO[i][j] = 0.f;
    float runM = -3.0e38f, runL = 0.f;

    for (int n0 = 0; n0 < 1024; n0 += 128) {
        __syncthreads();  // previous tile consumers done
        // keys: sf[k][n] = f[b][k][n0+n]
#pragma unroll
        for (int i = 0; i < 16; i++) {
            int e = t + i * 256; int k = e >> 7, nn = e & 127;
            sf[k * PADF + nn] = d_fp[((size_t)b * 32 + k) * 1024 + n0 + nn];
        }
        // values: sv[n][c] = hh[b][c][n0+n]  (float4 over n)
#pragma unroll
        for (int i = 0; i < 16; i++) {
            int e = t + i * 256; int c = e >> 5, n4 = e & 31;
            float4 hv = *(const float4*)(d_hp + ((size_t)b * 128 + c) * 1024 + n0 + n4 * 4);
            sv[(n4 * 4 + 0) * PADV + c] = hv.x;
            sv[(n4 * 4 + 1) * PADV + c] = hv.y;
            sv[(n4 * 4 + 2) * PADV + c] = hv.z;
            sv[(n4 * 4 + 3) * PADV + c] = hv.w;
        }
        __syncthreads();

        // ---- logits GEMM: S[n][m], thread owns 4 n x 8 m ----
        {
            float accS[4][8];
#pragma unroll
            for (int i = 0; i < 4; i++)
#pragma unroll
                for (int j = 0; j < 8; j++) accS[i][j] = 0.f;
#pragma unroll
            for (int k = 0; k < 32; k++) {
                float fr[4], qr[8];
#pragma unroll
                for (int i = 0; i < 4; i++) fr[i] = sf[k * PADF + tyc * 4 + i];
#pragma unroll
                for (int j = 0; j < 8; j++) qr[j] = sg[k * 64 + txm * 8 + j];
#pragma unroll
                for (int i = 0; i < 4; i++)
#pragma unroll
                    for (int j = 0; j < 8; j++) accS[i][j] += fr[i] * qr[j];
            }
#pragma unroll
            for (int i = 0; i < 4; i++) {
                float4 a0 = make_float4(accS[i][0], accS[i][1], accS[i][2], accS[i][3]);
                float4 a1 = make_float4(accS[i][4], accS[i][5], accS[i][6], accS[i][7]);
                *(float4*)(sp + (tyc * 4 + i) * PADP + txm * 8)     = a0;
                *(float4*)(sp + (tyc * 4 + i) * PADP + txm * 8 + 4) = a1;
            }
        }
        __syncthreads();

        // ---- online softmax over n, 4 threads per column msm ----
        float tmax = -3.0e38f;
#pragma unroll
        for (int nn = 0; nn < 32; nn++)
            tmax = fmaxf(tmax, sp[(q * 32 + nn) * PADP + msm]);
        sred[q * 64 + msm] = tmax;
        __syncthreads();
        float tileMax = fmaxf(fmaxf(sred[msm], sred[64 + msm]),
                              fmaxf(sred[128 + msm], sred[192 + msm]));
        float newM = fmaxf(runM, tileMax);
        float corr = __expf(runM - newM);
        if (q == 0) scorr[msm] = corr;
        float psum = 0.f;
#pragma unroll
        for (int nn = 0; nn < 32; nn++) {
            int ix = (q * 32 + nn) * PADP + msm;
            float p = __expf(sp[ix] - newM);
            sp[ix] = p;
            psum += p;
        }
        sred[256 + q * 64 + msm] = psum;
        __syncthreads();
        runL = runL * corr + (sred[256 + msm] + sred[320 + msm] + sred[384 + msm] + sred[448 + msm]);
        runM = newM;

        // ---- PV accumulate: accO[c_i][m_j] += v[n][c] * P[n][m] ----
        {
            float cr[8];
#pragma unroll
            for (int j = 0; j < 8; j++) cr[j] = scorr[txm * 8 + j];
#pragma unroll
            for (int i = 0; i < 4; i++)
#pragma unroll
                for (int j = 0; j < 8; j++) accO[i][j] *= cr[j];
#pragma unroll 2
            for (int n = 0; n < 128; n++) {
                float4 v4 = *(const float4*)(sv + n * PADV + tyc * 4);
                float4 p0 = *(const float4*)(sp + n * PADP + txm * 8);
                float4 p1 = *(const float4*)(sp + n * PADP + txm * 8 + 4);
                float vv[4] = { v4.x, v4.y, v4.z, v4.w };
                float pp[8] = { p0.x, p0.y, p0.z, p0.w, p1.x, p1.y, p1.z, p1.w };
#pragma unroll
                for (int i = 0; i < 4; i++)
#pragma unroll
                    for (int j = 0; j < 8; j++) accO[i][j] += vv[i] * pp[j];
            }
        }
    }

    __syncthreads();
    if (q == 0) sl[msm] = runL;
    __syncthreads();

    float inv[8];
#pragma unroll
    for (int j = 0; j < 8; j++) inv[j] = 1.0f / sl[txm * 8 + j];
#pragma unroll
    for (int i = 0; i < 4; i++) {
        size_t off = ((size_t)b * 128 + tyc * 4 + i) * HW + m0 + txm * 8;
        float4 o0 = make_float4(accO[i][0] * inv[0], accO[i][1] * inv[1],
                                accO[i][2] * inv[2], accO[i][3] * inv[3]);
        float4 o1 = make_float4(accO[i][4] * inv[4], accO[i][5] * inv[5],
                                accO[i][6] * inv[6], accO[i][7] * inv[7]);
        *(float4*)(d_ov + off)     = o0;
        *(float4*)(d_ov + off + 4) = o1;
    }
}

// ---------------- launch ----------------
extern "C" void kernel_launch(void* const* d_in, const int* in_sizes, int n_in,
                              void* d_out, int out_size)
{
    const float* x  = (const float*)d_in[0];
    const float* w1 = (const float*)d_in[1],  *b1 = (const float*)d_in[2],
               *s1 = (const float*)d_in[3],  *t1 = (const float*)d_in[4],
               *m1 = (const float*)d_in[5],  *v1 = (const float*)d_in[6];
    const float* w2 = (const float*)d_in[7],  *b2 = (const float*)d_in[8],
               *s2 = (const float*)d_in[9],  *t2 = (const float*)d_in[10],
               *m2 = (const float*)d_in[11], *v2 = (const float*)d_in[12];
    const float* w3 = (const float*)d_in[13], *b3 = (const float*)d_in[14],
               *s3 = (const float*)d_in[15], *t3 = (const float*)d_in[16],
               *m3 = (const float*)d_in[17], *v3 = (const float*)d_in[18];
    const float* w4 = (const float*)d_in[19], *b4 = (const float*)d_in[20],
               *s4 = (const float*)d_in[21], *t4 = (const float*)d_in[22],
               *m4 = (const float*)d_in[23], *v4 = (const float*)d_in[24];
    const float* gamma = (const float*)d_in[25];
    float* out = (float*)d_out;

    const int attn_smem = (32 * 64 + 32 * PADF + 128 * PADV + 128 * PADP + 512 + 64 + 64) * 4;
    cudaFuncSetAttribute(attn_kernel, cudaFuncAttributeMaxDynamicSharedMemorySize, attn_smem);

    prep_kernel<<<192, 256>>>(w1, b1, s1, t1, m1, v1,
                              w2, b2, s2, t2, m2, v2,
                              w3, b3, s3, t3, m3, v3,
                              w4, b4, s4, t4, m4, v4);

    gemm_kernel<0><<<dim3(32, 3, 8), 256>>>(x, nullptr, nullptr);

    pool_kernel<<<(8 * 160 * 1024 + 255) / 256, 256>>>();

    attn_kernel<<<dim3(64, 8), 256, attn_smem>>>();

    gemm_kernel<1><<<dim3(32, 4, 8), 256>>>(x, out, gamma);
}